// round 14
// baseline (speedup 1.0000x reference)
#include <cuda_runtime.h>
#include <cuda_fp16.h>
#include <cstdint>

#define Bsz 1024
#define Tsz 256
#define Dsz 128
#define Hsz 64
#define G4  256   // 4*H

// 128 MB fp16 scratch, layout [t][b][g_permuted]
__device__ __half g_xp16[Tsz * Bsz * G4];

// permuted col p -> original gate row
__device__ __host__ __forceinline__ int orig_gate(int p) {
    int w_  = p >> 5;
    int nt_ = (p >> 3) & 3;
    int lc_ = p & 7;
    return 64 * (lc_ & 3) + 8 * w_ + 2 * nt_ + (lc_ >> 2);
}

__device__ __forceinline__ uint32_t smem_u32(const void* p) {
    uint32_t a;
    asm("{ .reg .u64 t; cvta.to.shared.u64 t, %1; cvt.u32.u64 %0, t; }"
        : "=r"(a) : "l"(p));
    return a;
}

__device__ __forceinline__ void ldsm_x4(uint32_t* r, uint32_t addr) {
    asm volatile("ldmatrix.sync.aligned.m8n8.x4.shared.b16 {%0,%1,%2,%3}, [%4];"
                 : "=r"(r[0]), "=r"(r[1]), "=r"(r[2]), "=r"(r[3]) : "r"(addr));
}

// fp16-accumulator HMMA (2 output regs = 4 halves)
__device__ __forceinline__ void mma16816h(uint32_t* d, const uint32_t* a,
                                          uint32_t b0, uint32_t b1) {
    asm volatile(
        "mma.sync.aligned.m16n8k16.row.col.f16.f16.f16.f16 "
        "{%0,%1}, {%2,%3,%4,%5}, {%6,%7}, {%0,%1};"
        : "+r"(d[0]), "+r"(d[1])
        : "r"(a[0]), "r"(a[1]), "r"(a[2]), "r"(a[3]), "r"(b0), "r"(b1));
}

__device__ __forceinline__ uint32_t h2(float a, float b) {
    __half2 h = __floats2half2_rn(a, b);
    return *(uint32_t*)&h;
}

// ===========================================================================
// Kernel A: x_proj = x @ W_ih^T (permuted cols), fp16-acc HMMA, fp16 output,
// smem-staged coalesced stores. 1024 CTAs x 2 tiles.
// ===========================================================================
#define GEMM_CTAS     1024
#define TILES_PER_CTA 2
#define TM 128
#define STRB 272
#define A_BYTES (128 * STRB)
#define B_BYTES (256 * STRB)
#define OFF_A 0
#define OFF_B (A_BYTES)
#define OFF_ST (A_BYTES + B_BYTES)
#define STG_STR 264
#define STAGE_BYTES (128 * STG_STR * 2)
#define GEMM_SMEM (OFF_ST + STAGE_BYTES + 64)

__global__ __launch_bounds__(512, 1) void xproj_tc(
    const float* __restrict__ x,
    const float* __restrict__ Wih)
{
    extern __shared__ char dyn[];
    char* base = (char*)(((uintptr_t)dyn + 1023) & ~(uintptr_t)1023);

    const int tid  = threadIdx.x;
    const int lane = tid & 31;
    const int warp = tid >> 5;
    const int mrow_off = (warp & 7) * 16;
    const int ncol_off = (warp >> 3) * 128;

    // convert B (Wih fp32 -> fp16 smem), rows permuted
    {
        const int row  = tid >> 1;
        const int koff = (tid & 1) * 64;
        const int og   = orig_gate(row);
        const float4* src = (const float4*)(Wih + (size_t)og * Dsz + koff);
        char* bh = base + OFF_B + row * STRB + koff * 2;
#pragma unroll
        for (int q = 0; q < 16; q++) {
            float4 v = src[q];
            *(uint2*)(bh + q * 8) = make_uint2(h2(v.x, v.y), h2(v.z, v.w));
        }
    }

    const uint32_t sA = smem_u32(base + OFF_A);
    const uint32_t sB = smem_u32(base + OFF_B);
    __half* stg = (__half*)(base + OFF_ST);

    const uint32_t a_lane = (uint32_t)(mrow_off + (lane & 15)) * STRB + (lane >> 4) * 16;
    const uint32_t b_lane = (uint32_t)(ncol_off + ((lane >> 4) << 3) + (lane & 7)) * STRB
                          + ((lane >> 3) & 1) * 16;

    const int conv_row  = tid >> 2;
    const int conv_koff = (tid & 3) * 32;

    for (int i = 0; i < TILES_PER_CTA; i++) {
        const size_t tile_m = (size_t)(blockIdx.x * TILES_PER_CTA + i) * TM;

        __syncthreads();

        // convert A tile (128x128 fp32 -> fp16 smem)
        {
            const float4* src = (const float4*)(x + (tile_m + conv_row) * Dsz + conv_koff);
            char* ah = base + OFF_A + conv_row * STRB + conv_koff * 2;
#pragma unroll
            for (int q = 0; q < 8; q++) {
                float4 v = src[q];
                *(uint2*)(ah + q * 8) = make_uint2(h2(v.x, v.y), h2(v.z, v.w));
            }
        }
        __syncthreads();

        uint32_t acc[16][2];
#pragma unroll
        for (int j = 0; j < 16; j++) { acc[j][0] = 0u; acc[j][1] = 0u; }

#pragma unroll
        for (int ks = 0; ks < 8; ks++) {
            uint32_t ra[4];
            ldsm_x4(ra, sA + a_lane + ks * 32);
#pragma unroll
            for (int j = 0; j < 8; j++) {
                uint32_t rb[4];
                ldsm_x4(rb, sB + b_lane + j * (16 * STRB) + ks * 32);
                mma16816h(acc[2 * j],     ra, rb[0], rb[1]);
                mma16816h(acc[2 * j + 1], ra, rb[2], rb[3]);
            }
        }

        // stage acc (already fp16) -> smem
        {
            const int g  = lane >> 2;
            const int tc = lane & 3;
            const int r_lo = mrow_off + g;
            const int r_hi = r_lo + 8;
#pragma unroll
            for (int j = 0; j < 16; j++) {
                const int col = ncol_off + 2 * tc + 8 * j;
                *(uint32_t*)(stg + r_lo * STG_STR + col) = acc[j][0];
                *(uint32_t*)(stg + r_hi * STG_STR + col) = acc[j][1];
            }
        }
        __syncthreads();

        // coalesced write-out: warp w handles rows 8w..8w+7 (512B each)
        {
            const int b_idx  = (int)(tile_m >> 8);
            const int t_base = (int)(tile_m & 255);
#pragma unroll
            for (int r = 0; r < 8; r++) {
                const int sr = 8 * warp + r;
                __half* dst = g_xp16 + ((size_t)(t_base + sr) * Bsz + b_idx) * G4;
                uint4 v = *(const uint4*)(stg + sr * STG_STR + lane * 8);
                *(uint4*)(dst + lane * 8) = v;
            }
        }
    }
}

// ===========================================================================
// Kernel B: tensor-core LSTM recurrence, fp16-acc HMMA, permuted gates,
// single-shfl intra-warp exchange, one barrier/step. 64 blocks x 256 threads.
// ===========================================================================
#define RB   16
#define HSTR 72
#define HBUFB (RB * HSTR * 2)

#define SM_HA    0
#define SM_WHS   (2 * HBUFB)
#define SM_TOTAL (SM_WHS + 256 * HSTR * 2)

__device__ __forceinline__ float tanhap(float x) {
    float y;
    asm("tanh.approx.f32 %0, %1;" : "=f"(y) : "f"(x));
    return y;
}
__device__ __forceinline__ float sigm_ap(float x) {
    return fmaf(0.5f, tanhap(0.5f * x), 0.5f);
}
__device__ __forceinline__ float sigm_exact(float v) {
    return __fdividef(1.f, 1.f + __expf(-v));
}

__global__ __launch_bounds__(256, 1) void lstm_rec_tc(
    const float* __restrict__ Whh,
    const float* __restrict__ bih, const float* __restrict__ bhh,
    const float* __restrict__ W1, const float* __restrict__ b1,
    const float* __restrict__ W2, const float* __restrict__ b2,
    float* __restrict__ out)
{
    __shared__ __align__(16) char sm[SM_TOTAL];
    __half* hA  = (__half*)(sm + SM_HA);     // [2][RB][HSTR]
    __half* WhS = (__half*)(sm + SM_WHS);    // [256][HSTR] permuted Whh

    const int tid  = threadIdx.x;
    const int lane = tid & 31;
    const int w    = tid >> 5;
    const int rq   = lane >> 2;
    const int q    = lane & 3;
    const bool even = (q & 1) == 0;
    const int r0   = blockIdx.x * RB;

    // stage permuted Whh fp32 -> fp16 smem
    {
        const int p  = tid;
        const int og = orig_gate(p);
        const float4* src = (const float4*)(Whh + (size_t)og * Hsz);
        __half* dst = WhS + p * HSTR;
#pragma unroll
        for (int qq = 0; qq < 16; qq++) {
            float4 v = src[qq];
            *(uint2*)(dst + qq * 4) = make_uint2(h2(v.x, v.y), h2(v.z, v.w));
        }
    }
    __syncthreads();

    // preload B fragments
    uint32_t rbf[4][8];
    {
        const uint32_t sW = smem_u32(WhS);
        const uint32_t bl1 = (uint32_t)(32 * w + ((lane >> 4) << 3) + (lane & 7)) * (HSTR * 2)
                           + ((lane >> 3) & 1) * 16;
        const uint32_t bl2 = bl1 + 16 * (HSTR * 2);
#pragma unroll
        for (int kt = 0; kt < 4; kt++) {
            uint32_t r1[4], r2[4];
            ldsm_x4(r1, sW + bl1 + kt * 32);
            ldsm_x4(r2, sW + bl2 + kt * 32);
            rbf[kt][0] = r1[0]; rbf[kt][1] = r1[1];
            rbf[kt][2] = r1[2]; rbf[kt][3] = r1[3];
            rbf[kt][4] = r2[0]; rbf[kt][5] = r2[1];
            rbf[kt][6] = r2[2]; rbf[kt][7] = r2[3];
        }
    }

    for (int i = tid; i < 2 * RB * HSTR; i += 256) hA[i] = __float2half(0.f);

    // bias as packed half2 per n-tile
    uint32_t bias2[4];
#pragma unroll
    for (int nt = 0; nt < 4; nt++) {
        int p0 = 32 * w + 8 * nt + 2 * q;
        bias2[nt] = h2(bih[orig_gate(p0)] + bhh[orig_gate(p0)],
                       bih[orig_gate(p0 + 1)] + bhh[orig_gate(p0 + 1)]);
    }

    const size_t tstep  = (size_t)Bsz * G4;
    const size_t baseA0 = (size_t)(r0 + rq) * G4 + 32 * w + 2 * q;
    const size_t baseB0 = (size_t)(r0 + rq + 8) * G4 + 32 * w + 2 * q;

    uint32_t xbA[2][4], xbB[2][4];
#pragma unroll
    for (int nt = 0; nt < 4; nt++) {
        xbA[0][nt] = *(const uint32_t*)(g_xp16 + baseA0 + nt * 8);
        xbB[0][nt] = *(const uint32_t*)(g_xp16 + baseB0 + nt * 8);
        xbA[1][nt] = *(const uint32_t*)(g_xp16 + tstep + baseA0 + nt * 8);
        xbB[1][nt] = *(const uint32_t*)(g_xp16 + tstep + baseB0 + nt * 8);
    }

    float c[4] = {0.f, 0.f, 0.f, 0.f};

    const uint32_t sHA = smem_u32(hA);
    const uint32_t a_lane_base = (uint32_t)(lane & 15) * (HSTR * 2) + (lane >> 4) * 16;

    const int prow  = even ? rq : rq + 8;
    const int ubase = 8 * w + (q >> 1);

    __syncthreads();

#pragma unroll 2
    for (int t = 0; t < Tsz; t++) {
        const int cur = t & 1;

        // acc init = bias + xproj  (HADD2 on packed half2)
        uint32_t acc[4][2];
#pragma unroll
        for (int nt = 0; nt < 4; nt++) {
            __half2 v0 = __hadd2(*(__half2*)&bias2[nt], *(__half2*)&xbA[cur][nt]);
            __half2 v1 = __hadd2(*(__half2*)&bias2[nt], *(__half2*)&xbB[cur][nt]);
            acc[nt][0] = *(uint32_t*)&v0;
            acc[nt][1] = *(uint32_t*)&v1;
        }

        // reissue buf[cur] for t+2
        {
            const size_t tn = (size_t)((t + 2 < Tsz) ? t + 2 : Tsz - 1) * tstep;
#pragma unroll
            for (int nt = 0; nt < 4; nt++) {
                xbA[cur][nt] = *(const uint32_t*)(g_xp16 + tn + baseA0 + nt * 8);
                xbB[cur][nt] = *(const uint32_t*)(g_xp16 + tn + baseB0 + nt * 8);
            }
        }

        // matvec (fp16 acc)
        const uint32_t aL = sHA + cur * HBUFB + a_lane_base;
        uint32_t ra[4][4];
        ldsm_x4(ra[0], aL + 0 * 32);
        ldsm_x4(ra[1], aL + 1 * 32);
        ldsm_x4(ra[2], aL + 2 * 32);
        ldsm_x4(ra[3], aL + 3 * 32);
#pragma unroll
        for (int kt = 0; kt < 4; kt++) {
            mma16816h(acc[0], ra[kt], rbf[kt][0], rbf[kt][1]);
            mma16816h(acc[1], ra[kt], rbf[kt][2], rbf[kt][3]);
            mma16816h(acc[2], ra[kt], rbf[kt][4], rbf[kt][5]);
            mma16816h(acc[3], ra[kt], rbf[kt][6], rbf[kt][7]);
        }

        // single-shfl gate exchange + pointwise; write h to buf nxt
        // reg0 = row rq {pair}, reg1 = row rq+8 {pair}; even pair={i,f}, odd={g,o}
        __half* hnext = (__half*)(sm + SM_HA + ((t + 1) & 1) * HBUFB);
#pragma unroll
        for (int nt = 0; nt < 4; nt++) {
            uint32_t own  = even ? acc[nt][0] : acc[nt][1];
            uint32_t send = even ? acc[nt][1] : acc[nt][0];
            uint32_t recv = __shfl_xor_sync(0xffffffffu, send, 1);

            float2 f_if = __half22float2(even ? *(__half2*)&own  : *(__half2*)&recv);
            float2 f_go = __half22float2(even ? *(__half2*)&recv : *(__half2*)&own);

            float vi = sigm_ap(f_if.x);
            float vf = sigm_ap(f_if.y);
            float vg = tanhap(f_go.x);
            float vo = sigm_ap(f_go.y);
            c[nt] = fmaf(vf, c[nt], vi * vg);
            float hv = vo * tanhap(c[nt]);

            hnext[prow * HSTR + ubase + 2 * nt] = __float2half(hv);
        }
        __syncthreads();
    }

    // fused head (exact sigmoid)
    {
        __half* hfin = (__half*)(sm + SM_HA + (Tsz & 1) * HBUFB);
#pragma unroll
        for (int rr = w; rr < RB; rr += 8) {
            float y1 = b1[lane];
#pragma unroll
            for (int k = 0; k < Hsz; k++)
                y1 += W1[lane * Hsz + k] * __half2float(hfin[rr * HSTR + k]);
            y1 = fmaxf(y1, 0.f);
            float z = y1 * W2[lane];
#pragma unroll
            for (int off = 16; off > 0; off >>= 1) z += __shfl_down_sync(0xffffffffu, z, off);
            if (lane == 0) out[r0 + rr] = sigm_exact(z + b2[0]);
        }
    }
}

// ===========================================================================
extern "C" void kernel_launch(void* const* d_in, const int* in_sizes, int n_in,
                              void* d_out, int out_size)
{
    const float* x   = (const float*)d_in[0];
    const float* Wih = (const float*)d_in[1];
    const float* Whh = (const float*)d_in[2];
    const float* bih = (const float*)d_in[3];
    const float* bhh = (const float*)d_in[4];
    const float* W1  = (const float*)d_in[5];
    const float* b1  = (const float*)d_in[6];
    const float* W2  = (const float*)d_in[7];
    const float* b2  = (const float*)d_in[8];
    float* out = (float*)d_out;

    static bool attr_set = false;
    if (!attr_set) {
        cudaFuncSetAttribute(xproj_tc, cudaFuncAttributeMaxDynamicSharedMemorySize, GEMM_SMEM);
        attr_set = true;
    }
    xproj_tc<<<GEMM_CTAS, 512, GEMM_SMEM>>>(x, Wih);
    lstm_rec_tc<<<Bsz / RB, 256>>>(Whh, bih, bhh, W1, b1, W2, b2, out);
}

// round 16
// speedup vs baseline: 1.0046x; 1.0046x over previous
#include <cuda_runtime.h>
#include <cuda_fp16.h>
#include <cstdint>

#define Bsz 1024
#define Tsz 256
#define Dsz 128
#define Hsz 64
#define G4  256   // 4*H

// 128 MB fp16 scratch, layout [t][b][g_permuted]
__device__ __half g_xp16[Tsz * Bsz * G4];

// permuted col p -> original gate row
__device__ __host__ __forceinline__ int orig_gate(int p) {
    int w_  = p >> 5;
    int nt_ = (p >> 3) & 3;
    int lc_ = p & 7;
    return 64 * (lc_ & 3) + 8 * w_ + 2 * nt_ + (lc_ >> 2);
}

__device__ __forceinline__ uint32_t smem_u32(const void* p) {
    uint32_t a;
    asm("{ .reg .u64 t; cvta.to.shared.u64 t, %1; cvt.u32.u64 %0, t; }"
        : "=r"(a) : "l"(p));
    return a;
}

__device__ __forceinline__ void ldsm_x4(uint32_t* r, uint32_t addr) {
    asm volatile("ldmatrix.sync.aligned.m8n8.x4.shared.b16 {%0,%1,%2,%3}, [%4];"
                 : "=r"(r[0]), "=r"(r[1]), "=r"(r[2]), "=r"(r[3]) : "r"(addr));
}

__device__ __forceinline__ void mma16816(float* d, const uint32_t* a,
                                         uint32_t b0, uint32_t b1) {
    asm volatile(
        "mma.sync.aligned.m16n8k16.row.col.f32.f16.f16.f32 "
        "{%0,%1,%2,%3}, {%4,%5,%6,%7}, {%8,%9}, {%0,%1,%2,%3};"
        : "+f"(d[0]), "+f"(d[1]), "+f"(d[2]), "+f"(d[3])
        : "r"(a[0]), "r"(a[1]), "r"(a[2]), "r"(a[3]), "r"(b0), "r"(b1));
}

__device__ __forceinline__ uint32_t h2(float a, float b) {
    __half2 h = __floats2half2_rn(a, b);
    return *(uint32_t*)&h;
}

// ===========================================================================
// Kernel A: x_proj = x @ W_ih^T (permuted cols), fp32-acc fp16 HMMA,
// fp16 output, smem-staged coalesced stores. 1024 CTAs x 2 tiles.
// (identical to R13 — 148 us)
// ===========================================================================
#define GEMM_CTAS     1024
#define TILES_PER_CTA 2
#define TM 128
#define STRB 272
#define A_BYTES (128 * STRB)
#define B_BYTES (256 * STRB)
#define OFF_A 0
#define OFF_B (A_BYTES)
#define OFF_ST (A_BYTES + B_BYTES)
#define STG_STR 264
#define STAGE_BYTES (128 * STG_STR * 2)
#define GEMM_SMEM (OFF_ST + STAGE_BYTES + 64)

__global__ __launch_bounds__(512, 1) void xproj_tc(
    const float* __restrict__ x,
    const float* __restrict__ Wih)
{
    extern __shared__ char dyn[];
    char* base = (char*)(((uintptr_t)dyn + 1023) & ~(uintptr_t)1023);

    const int tid  = threadIdx.x;
    const int lane = tid & 31;
    const int warp = tid >> 5;
    const int mrow_off = (warp & 7) * 16;
    const int ncol_off = (warp >> 3) * 128;

    {
        const int row  = tid >> 1;
        const int koff = (tid & 1) * 64;
        const int og   = orig_gate(row);
        const float4* src = (const float4*)(Wih + (size_t)og * Dsz + koff);
        char* bh = base + OFF_B + row * STRB + koff * 2;
#pragma unroll
        for (int q = 0; q < 16; q++) {
            float4 v = src[q];
            *(uint2*)(bh + q * 8) = make_uint2(h2(v.x, v.y), h2(v.z, v.w));
        }
    }

    const uint32_t sA = smem_u32(base + OFF_A);
    const uint32_t sB = smem_u32(base + OFF_B);
    __half* stg = (__half*)(base + OFF_ST);

    const uint32_t a_lane = (uint32_t)(mrow_off + (lane & 15)) * STRB + (lane >> 4) * 16;
    const uint32_t b_lane = (uint32_t)(ncol_off + ((lane >> 4) << 3) + (lane & 7)) * STRB
                          + ((lane >> 3) & 1) * 16;

    const int conv_row  = tid >> 2;
    const int conv_koff = (tid & 3) * 32;

    for (int i = 0; i < TILES_PER_CTA; i++) {
        const size_t tile_m = (size_t)(blockIdx.x * TILES_PER_CTA + i) * TM;

        __syncthreads();

        {
            const float4* src = (const float4*)(x + (tile_m + conv_row) * Dsz + conv_koff);
            char* ah = base + OFF_A + conv_row * STRB + conv_koff * 2;
#pragma unroll
            for (int q = 0; q < 8; q++) {
                float4 v = src[q];
                *(uint2*)(ah + q * 8) = make_uint2(h2(v.x, v.y), h2(v.z, v.w));
            }
        }
        __syncthreads();

        float acc[16][4];
#pragma unroll
        for (int j = 0; j < 16; j++)
#pragma unroll
            for (int q = 0; q < 4; q++) acc[j][q] = 0.f;

#pragma unroll
        for (int ks = 0; ks < 8; ks++) {
            uint32_t ra[4];
            ldsm_x4(ra, sA + a_lane + ks * 32);
#pragma unroll
            for (int j = 0; j < 8; j++) {
                uint32_t rb[4];
                ldsm_x4(rb, sB + b_lane + j * (16 * STRB) + ks * 32);
                mma16816(acc[2 * j],     ra, rb[0], rb[1]);
                mma16816(acc[2 * j + 1], ra, rb[2], rb[3]);
            }
        }

        {
            const int g  = lane >> 2;
            const int tc = lane & 3;
            const int r_lo = mrow_off + g;
            const int r_hi = r_lo + 8;
#pragma unroll
            for (int j = 0; j < 16; j++) {
                const int col = ncol_off + 2 * tc + 8 * j;
                *(__half2*)(stg + r_lo * STG_STR + col) =
                    __floats2half2_rn(acc[j][0], acc[j][1]);
                *(__half2*)(stg + r_hi * STG_STR + col) =
                    __floats2half2_rn(acc[j][2], acc[j][3]);
            }
        }
        __syncthreads();

        {
            const int b_idx  = (int)(tile_m >> 8);
            const int t_base = (int)(tile_m & 255);
#pragma unroll
            for (int r = 0; r < 8; r++) {
                const int sr = 8 * warp + r;
                __half* dst = g_xp16 + ((size_t)(t_base + sr) * Bsz + b_idx) * G4;
                uint4 v = *(const uint4*)(stg + sr * STG_STR + lane * 8);
                *(uint4*)(dst + lane * 8) = v;
            }
        }
    }
}

// ===========================================================================
// Kernel B: tensor-core LSTM recurrence (R13 structure) with the MMA
// dependency chain broken: 4 INDEPENDENT MMAs per n-tile (one per k-tile),
// folded by a 2-level FADD tree. Chain/step = 1 HMMA latency, not 4.
// ===========================================================================
#define RB   16
#define HSTR 72
#define HBUFB (RB * HSTR * 2)

#define SM_HA    0
#define SM_WHS   (2 * HBUFB)
#define SM_TOTAL (SM_WHS + 256 * HSTR * 2)

__device__ __forceinline__ float tanhap(float x) {
    float y;
    asm("tanh.approx.f32 %0, %1;" : "=f"(y) : "f"(x));
    return y;
}
__device__ __forceinline__ float sigm_ap(float x) {
    return fmaf(0.5f, tanhap(0.5f * x), 0.5f);
}
__device__ __forceinline__ float sigm_exact(float v) {
    return __fdividef(1.f, 1.f + __expf(-v));
}

__global__ __launch_bounds__(256, 1) void lstm_rec_tc(
    const float* __restrict__ Whh,
    const float* __restrict__ bih, const float* __restrict__ bhh,
    const float* __restrict__ W1, const float* __restrict__ b1,
    const float* __restrict__ W2, const float* __restrict__ b2,
    float* __restrict__ out)
{
    __shared__ __align__(16) char sm[SM_TOTAL];
    __half* hA  = (__half*)(sm + SM_HA);     // [2][RB][HSTR]
    __half* WhS = (__half*)(sm + SM_WHS);    // [256][HSTR] permuted Whh

    const int tid  = threadIdx.x;
    const int lane = tid & 31;
    const int w    = tid >> 5;
    const int rq   = lane >> 2;
    const int q    = lane & 3;
    const bool even = (q & 1) == 0;
    const int r0   = blockIdx.x * RB;

    // stage permuted Whh fp32 -> fp16 smem
    {
        const int p  = tid;
        const int og = orig_gate(p);
        const float4* src = (const float4*)(Whh + (size_t)og * Hsz);
        __half* dst = WhS + p * HSTR;
#pragma unroll
        for (int qq = 0; qq < 16; qq++) {
            float4 v = src[qq];
            *(uint2*)(dst + qq * 4) = make_uint2(h2(v.x, v.y), h2(v.z, v.w));
        }
    }
    __syncthreads();

    // preload B fragments: 4 kt x 4 n-tiles
    uint32_t rbf[4][8];
    {
        const uint32_t sW = smem_u32(WhS);
        const uint32_t bl1 = (uint32_t)(32 * w + ((lane >> 4) << 3) + (lane & 7)) * (HSTR * 2)
                           + ((lane >> 3) & 1) * 16;
        const uint32_t bl2 = bl1 + 16 * (HSTR * 2);
#pragma unroll
        for (int kt = 0; kt < 4; kt++) {
            uint32_t r1[4], r2[4];
            ldsm_x4(r1, sW + bl1 + kt * 32);
            ldsm_x4(r2, sW + bl2 + kt * 32);
            rbf[kt][0] = r1[0]; rbf[kt][1] = r1[1];
            rbf[kt][2] = r1[2]; rbf[kt][3] = r1[3];
            rbf[kt][4] = r2[0]; rbf[kt][5] = r2[1];
            rbf[kt][6] = r2[2]; rbf[kt][7] = r2[3];
        }
    }

    for (int i = tid; i < 2 * RB * HSTR; i += 256) hA[i] = __float2half(0.f);

    // bias fragments
    float2 biasv[4];
#pragma unroll
    for (int nt = 0; nt < 4; nt++) {
        int p0 = 32 * w + 8 * nt + 2 * q;
        biasv[nt] = make_float2(bih[orig_gate(p0)] + bhh[orig_gate(p0)],
                                bih[orig_gate(p0 + 1)] + bhh[orig_gate(p0 + 1)]);
    }

    const size_t tstep  = (size_t)Bsz * G4;
    const size_t baseA0 = (size_t)(r0 + rq) * G4 + 32 * w + 2 * q;
    const size_t baseB0 = (size_t)(r0 + rq + 8) * G4 + 32 * w + 2 * q;

    uint32_t xbA[2][4], xbB[2][4];
#pragma unroll
    for (int nt = 0; nt < 4; nt++) {
        xbA[0][nt] = *(const uint32_t*)(g_xp16 + baseA0 + nt * 8);
        xbB[0][nt] = *(const uint32_t*)(g_xp16 + baseB0 + nt * 8);
        xbA[1][nt] = *(const uint32_t*)(g_xp16 + tstep + baseA0 + nt * 8);
        xbB[1][nt] = *(const uint32_t*)(g_xp16 + tstep + baseB0 + nt * 8);
    }

    float c[4] = {0.f, 0.f, 0.f, 0.f};

    const uint32_t sHA = smem_u32(hA);
    const uint32_t a_lane_base = (uint32_t)(lane & 15) * (HSTR * 2) + (lane >> 4) * 16;

    const int prow  = even ? rq : rq + 8;
    const int ubase = 8 * w + (q >> 1);

    __syncthreads();

#pragma unroll 2
    for (int t = 0; t < Tsz; t++) {
        const int cur = t & 1;

        // 4 independent partial accumulators per n-tile (one per k-tile).
        // p[0] starts from bias+xproj; p[1..3] start from zero.
        float p0[4][4], p1[4][4], p2[4][4], p3[4][4];
#pragma unroll
        for (int nt = 0; nt < 4; nt++) {
            float2 xa = __half22float2(*(__half2*)&xbA[cur][nt]);
            float2 xb = __half22float2(*(__half2*)&xbB[cur][nt]);
            p0[nt][0] = biasv[nt].x + xa.x;
            p0[nt][1] = biasv[nt].y + xa.y;
            p0[nt][2] = biasv[nt].x + xb.x;
            p0[nt][3] = biasv[nt].y + xb.y;
#pragma unroll
            for (int qq = 0; qq < 4; qq++) {
                p1[nt][qq] = 0.f; p2[nt][qq] = 0.f; p3[nt][qq] = 0.f;
            }
        }

        // reissue buf[cur] for t+2
        {
            const size_t tn = (size_t)((t + 2 < Tsz) ? t + 2 : Tsz - 1) * tstep;
#pragma unroll
            for (int nt = 0; nt < 4; nt++) {
                xbA[cur][nt] = *(const uint32_t*)(g_xp16 + tn + baseA0 + nt * 8);
                xbB[cur][nt] = *(const uint32_t*)(g_xp16 + tn + baseB0 + nt * 8);
            }
        }

        // matvec: 16 fully-independent MMAs (no inter-MMA RAW)
        const uint32_t aL = sHA + cur * HBUFB + a_lane_base;
        uint32_t ra[4][4];
        ldsm_x4(ra[0], aL + 0 * 32);
        ldsm_x4(ra[1], aL + 1 * 32);
        ldsm_x4(ra[2], aL + 2 * 32);
        ldsm_x4(ra[3], aL + 3 * 32);
#pragma unroll
        for (int nt = 0; nt < 4; nt++) {
            mma16816(p0[nt], ra[0], rbf[0][2 * nt], rbf[0][2 * nt + 1]);
            mma16816(p1[nt], ra[1], rbf[1][2 * nt], rbf[1][2 * nt + 1]);
            mma16816(p2[nt], ra[2], rbf[2][2 * nt], rbf[2][2 * nt + 1]);
            mma16816(p3[nt], ra[3], rbf[3][2 * nt], rbf[3][2 * nt + 1]);
        }

        // fold partials (2-level FADD tree), then intra-warp exchange + pointwise
        __half* hnext = (__half*)(sm + SM_HA + ((t + 1) & 1) * HBUFB);
#pragma unroll
        for (int nt = 0; nt < 4; nt++) {
            float a0 = (p0[nt][0] + p1[nt][0]) + (p2[nt][0] + p3[nt][0]);
            float a1 = (p0[nt][1] + p1[nt][1]) + (p2[nt][1] + p3[nt][1]);
            float a2 = (p0[nt][2] + p1[nt][2]) + (p2[nt][2] + p3[nt][2]);
            float a3 = (p0[nt][3] + p1[nt][3]) + (p2[nt][3] + p3[nt][3]);

            float s1 = even ? a2 : a0;
            float r1 = __shfl_xor_sync(0xffffffffu, s1, 1);
            float s2 = even ? a3 : a1;
            float r2 = __shfl_xor_sync(0xffffffffu, s2, 1);

            float vi = even ? a0 : r1;
            float vf = even ? a1 : r2;
            float vg = even ? r1 : a2;
            float vo = even ? r2 : a3;

            vi = sigm_ap(vi);
            vf = sigm_ap(vf);
            vg = tanhap(vg);
            vo = sigm_ap(vo);
            c[nt] = fmaf(vf, c[nt], vi * vg);
            float hv = vo * tanhap(c[nt]);

            hnext[prow * HSTR + ubase + 2 * nt] = __float2half(hv);
        }
        __syncthreads();
    }

    // fused head (exact sigmoid)
    {
        __half* hfin = (__half*)(sm + SM_HA + (Tsz & 1) * HBUFB);
#pragma unroll
        for (int rr = w; rr < RB; rr += 8) {
            float y1 = b1[lane];
#pragma unroll
            for (int k = 0; k < Hsz; k++)
                y1 += W1[lane * Hsz + k] * __half2float(hfin[rr * HSTR + k]);
            y1 = fmaxf(y1, 0.f);
            float z = y1 * W2[lane];
#pragma unroll
            for (int off = 16; off > 0; off >>= 1) z += __shfl_down_sync(0xffffffffu, z, off);
            if (lane == 0) out[r0 + rr] = sigm_exact(z + b2[0]);
        }
    }
}

// ===========================================================================
extern "C" void kernel_launch(void* const* d_in, const int* in_sizes, int n_in,
                              void* d_out, int out_size)
{
    const float* x   = (const float*)d_in[0];
    const float* Wih = (const float*)d_in[1];
    const float* Whh = (const float*)d_in[2];
    const float* bih = (const float*)d_in[3];
    const float* bhh = (const float*)d_in[4];
    const float* W1  = (const float*)d_in[5];
    const float* b1  = (const float*)d_in[6];
    const float* W2  = (const float*)d_in[7];
    const float* b2  = (const float*)d_in[8];
    float* out = (float*)d_out;

    static bool attr_set = false;
    if (!attr_set) {
        cudaFuncSetAttribute(xproj_tc, cudaFuncAttributeMaxDynamicSharedMemorySize, GEMM_SMEM);
        attr_set = true;
    }
    xproj_tc<<<GEMM_CTAS, 512, GEMM_SMEM>>>(x, Wih);
    lstm_rec_tc<<<Bsz / RB, 256>>>(Whh, bih, bhh, W1, b1, W2, b2, out);
}

// round 17
// speedup vs baseline: 1.1895x; 1.1840x over previous
#include <cuda_runtime.h>
#include <cuda_fp16.h>
#include <cstdint>

#define Bsz 1024
#define Tsz 256
#define Dsz 128
#define Hsz 64
#define G4  256   // 4*H

// 128 MB fp16 scratch, layout [t][b][g_permuted]
__device__ __half g_xp16[Tsz * Bsz * G4];

// permuted col p -> original gate row
__device__ __host__ __forceinline__ int orig_gate(int p) {
    int w_  = p >> 5;
    int nt_ = (p >> 3) & 3;
    int lc_ = p & 7;
    return 64 * (lc_ & 3) + 8 * w_ + 2 * nt_ + (lc_ >> 2);
}

__device__ __forceinline__ uint32_t smem_u32(const void* p) {
    uint32_t a;
    asm("{ .reg .u64 t; cvta.to.shared.u64 t, %1; cvt.u32.u64 %0, t; }"
        : "=r"(a) : "l"(p));
    return a;
}

__device__ __forceinline__ void ldsm_x4(uint32_t* r, uint32_t addr) {
    asm volatile("ldmatrix.sync.aligned.m8n8.x4.shared.b16 {%0,%1,%2,%3}, [%4];"
                 : "=r"(r[0]), "=r"(r[1]), "=r"(r[2]), "=r"(r[3]) : "r"(addr));
}

__device__ __forceinline__ void mma16816(float* d, const uint32_t* a,
                                         uint32_t b0, uint32_t b1) {
    asm volatile(
        "mma.sync.aligned.m16n8k16.row.col.f32.f16.f16.f32 "
        "{%0,%1,%2,%3}, {%4,%5,%6,%7}, {%8,%9}, {%0,%1,%2,%3};"
        : "+f"(d[0]), "+f"(d[1]), "+f"(d[2]), "+f"(d[3])
        : "r"(a[0]), "r"(a[1]), "r"(a[2]), "r"(a[3]), "r"(b0), "r"(b1));
}

__device__ __forceinline__ uint32_t h2(float a, float b) {
    __half2 h = __floats2half2_rn(a, b);
    return *(uint32_t*)&h;
}

// ===========================================================================
// Kernel A: x_proj = x @ W_ih^T (permuted cols), fp32-acc fp16 HMMA,
// fp16 output, smem-staged coalesced stores. (identical to R13 — 148 us)
// ===========================================================================
#define GEMM_CTAS     1024
#define TILES_PER_CTA 2
#define TM 128
#define STRB 272
#define A_BYTES (128 * STRB)
#define B_BYTES (256 * STRB)
#define OFF_A 0
#define OFF_B (A_BYTES)
#define OFF_ST (A_BYTES + B_BYTES)
#define STG_STR 264
#define STAGE_BYTES (128 * STG_STR * 2)
#define GEMM_SMEM (OFF_ST + STAGE_BYTES + 64)

__global__ __launch_bounds__(512, 1) void xproj_tc(
    const float* __restrict__ x,
    const float* __restrict__ Wih)
{
    extern __shared__ char dyn[];
    char* base = (char*)(((uintptr_t)dyn + 1023) & ~(uintptr_t)1023);

    const int tid  = threadIdx.x;
    const int lane = tid & 31;
    const int warp = tid >> 5;
    const int mrow_off = (warp & 7) * 16;
    const int ncol_off = (warp >> 3) * 128;

    {
        const int row  = tid >> 1;
        const int koff = (tid & 1) * 64;
        const int og   = orig_gate(row);
        const float4* src = (const float4*)(Wih + (size_t)og * Dsz + koff);
        char* bh = base + OFF_B + row * STRB + koff * 2;
#pragma unroll
        for (int q = 0; q < 16; q++) {
            float4 v = src[q];
            *(uint2*)(bh + q * 8) = make_uint2(h2(v.x, v.y), h2(v.z, v.w));
        }
    }

    const uint32_t sA = smem_u32(base + OFF_A);
    const uint32_t sB = smem_u32(base + OFF_B);
    __half* stg = (__half*)(base + OFF_ST);

    const uint32_t a_lane = (uint32_t)(mrow_off + (lane & 15)) * STRB + (lane >> 4) * 16;
    const uint32_t b_lane = (uint32_t)(ncol_off + ((lane >> 4) << 3) + (lane & 7)) * STRB
                          + ((lane >> 3) & 1) * 16;

    const int conv_row  = tid >> 2;
    const int conv_koff = (tid & 3) * 32;

    for (int i = 0; i < TILES_PER_CTA; i++) {
        const size_t tile_m = (size_t)(blockIdx.x * TILES_PER_CTA + i) * TM;

        __syncthreads();

        {
            const float4* src = (const float4*)(x + (tile_m + conv_row) * Dsz + conv_koff);
            char* ah = base + OFF_A + conv_row * STRB + conv_koff * 2;
#pragma unroll
            for (int q = 0; q < 8; q++) {
                float4 v = src[q];
                *(uint2*)(ah + q * 8) = make_uint2(h2(v.x, v.y), h2(v.z, v.w));
            }
        }
        __syncthreads();

        float acc[16][4];
#pragma unroll
        for (int j = 0; j < 16; j++)
#pragma unroll
            for (int q = 0; q < 4; q++) acc[j][q] = 0.f;

#pragma unroll
        for (int ks = 0; ks < 8; ks++) {
            uint32_t ra[4];
            ldsm_x4(ra, sA + a_lane + ks * 32);
#pragma unroll
            for (int j = 0; j < 8; j++) {
                uint32_t rb[4];
                ldsm_x4(rb, sB + b_lane + j * (16 * STRB) + ks * 32);
                mma16816(acc[2 * j],     ra, rb[0], rb[1]);
                mma16816(acc[2 * j + 1], ra, rb[2], rb[3]);
            }
        }

        {
            const int g  = lane >> 2;
            const int tc = lane & 3;
            const int r_lo = mrow_off + g;
            const int r_hi = r_lo + 8;
#pragma unroll
            for (int j = 0; j < 16; j++) {
                const int col = ncol_off + 2 * tc + 8 * j;
                *(__half2*)(stg + r_lo * STG_STR + col) =
                    __floats2half2_rn(acc[j][0], acc[j][1]);
                *(__half2*)(stg + r_hi * STG_STR + col) =
                    __floats2half2_rn(acc[j][2], acc[j][3]);
            }
        }
        __syncthreads();

        {
            const int b_idx  = (int)(tile_m >> 8);
            const int t_base = (int)(tile_m & 255);
#pragma unroll
            for (int r = 0; r < 8; r++) {
                const int sr = 8 * warp + r;
                __half* dst = g_xp16 + ((size_t)(t_base + sr) * Bsz + b_idx) * G4;
                uint4 v = *(const uint4*)(stg + sr * STG_STR + lane * 8);
                *(uint4*)(dst + lane * 8) = v;
            }
        }
    }
}

// ===========================================================================
// Kernel B: tensor-core LSTM recurrence, RB=8 rows/block, 128 blocks x 256
// threads — spreads MUFU/issue load over 128 SMs (was 64). MMA stays M=16
// with rows 8-15 pinned to zero. Pointwise: 2 cells/lane, full utilization.
// ===========================================================================
#define RB   8                        // real batch rows per block
#define MROWS 16                      // MMA tile rows (8 real + 8 zero)
#define HSTR 72
#define HBUFB (MROWS * HSTR * 2)      // 2304 per buffer

#define SM_HA    0
#define SM_WHS   (2 * HBUFB)          // 4608
#define SM_TOTAL (SM_WHS + 256 * HSTR * 2)

__device__ __forceinline__ float tanhap(float x) {
    float y;
    asm("tanh.approx.f32 %0, %1;" : "=f"(y) : "f"(x));
    return y;
}
__device__ __forceinline__ float sigm_ap(float x) {
    return fmaf(0.5f, tanhap(0.5f * x), 0.5f);
}
__device__ __forceinline__ float sigm_exact(float v) {
    return __fdividef(1.f, 1.f + __expf(-v));
}

__global__ __launch_bounds__(256, 1) void lstm_rec_tc(
    const float* __restrict__ Whh,
    const float* __restrict__ bih, const float* __restrict__ bhh,
    const float* __restrict__ W1, const float* __restrict__ b1,
    const float* __restrict__ W2, const float* __restrict__ b2,
    float* __restrict__ out)
{
    __shared__ __align__(16) char sm[SM_TOTAL];
    __half* hA  = (__half*)(sm + SM_HA);     // [2][MROWS][HSTR], rows 8-15 always 0
    __half* WhS = (__half*)(sm + SM_WHS);    // [256][HSTR] permuted Whh

    const int tid  = threadIdx.x;
    const int lane = tid & 31;
    const int w    = tid >> 5;
    const int rq   = lane >> 2;              // row 0..7
    const int q    = lane & 3;
    const bool even = (q & 1) == 0;
    const int r0   = blockIdx.x * RB;

    // stage permuted Whh fp32 -> fp16 smem
    {
        const int p  = tid;
        const int og = orig_gate(p);
        const float4* src = (const float4*)(Whh + (size_t)og * Hsz);
        __half* dst = WhS + p * HSTR;
#pragma unroll
        for (int qq = 0; qq < 16; qq++) {
            float4 v = src[qq];
            *(uint2*)(dst + qq * 4) = make_uint2(h2(v.x, v.y), h2(v.z, v.w));
        }
    }
    __syncthreads();

    // preload B fragments: 4 kt x 4 n-tiles
    uint32_t rbf[4][8];
    {
        const uint32_t sW = smem_u32(WhS);
        const uint32_t bl1 = (uint32_t)(32 * w + ((lane >> 4) << 3) + (lane & 7)) * (HSTR * 2)
                           + ((lane >> 3) & 1) * 16;
        const uint32_t bl2 = bl1 + 16 * (HSTR * 2);
#pragma unroll
        for (int kt = 0; kt < 4; kt++) {
            uint32_t r1[4], r2[4];
            ldsm_x4(r1, sW + bl1 + kt * 32);
            ldsm_x4(r2, sW + bl2 + kt * 32);
            rbf[kt][0] = r1[0]; rbf[kt][1] = r1[1];
            rbf[kt][2] = r1[2]; rbf[kt][3] = r1[3];
            rbf[kt][4] = r2[0]; rbf[kt][5] = r2[1];
            rbf[kt][6] = r2[2]; rbf[kt][7] = r2[3];
        }
    }

    // zero BOTH h buffers fully (rows 8-15 stay zero forever)
    for (int i = tid; i < 2 * MROWS * HSTR; i += 256) hA[i] = __float2half(0.f);

    // bias fragments (elements 0,1 only — rows rq)
    float2 biasv[4];
#pragma unroll
    for (int nt = 0; nt < 4; nt++) {
        int p0 = 32 * w + 8 * nt + 2 * q;
        biasv[nt] = make_float2(bih[orig_gate(p0)] + bhh[orig_gate(p0)],
                                bih[orig_gate(p0 + 1)] + bhh[orig_gate(p0 + 1)]);
    }

    const size_t tstep  = (size_t)Bsz * G4;
    const size_t baseA0 = (size_t)(r0 + rq) * G4 + 32 * w + 2 * q;

    // depth-2 prefetch (rows rq only)
    uint32_t xbA[2][4];
#pragma unroll
    for (int nt = 0; nt < 4; nt++) {
        xbA[0][nt] = *(const uint32_t*)(g_xp16 + baseA0 + nt * 8);
        xbA[1][nt] = *(const uint32_t*)(g_xp16 + tstep + baseA0 + nt * 8);
    }

    float cA = 0.f, cB = 0.f;   // two cells per lane

    const uint32_t sHA = smem_u32(hA);
    const uint32_t a_lane_base = (uint32_t)(lane & 15) * (HSTR * 2) + (lane >> 4) * 16;

    // pointwise units: even lanes own nt 0,1; odd own nt 2,3 (same row rq)
    const int uA = 8 * w + (even ? 0 : 4) + (q >> 1);
    const int uB = uA + 2;

    __syncthreads();

#pragma unroll 2
    for (int t = 0; t < Tsz; t++) {
        const int cur = t & 1;

        // acc init = bias + xproj (elements 0,1; 2,3 are garbage rows)
        float acc[4][4];
#pragma unroll
        for (int nt = 0; nt < 4; nt++) {
            float2 xa = __half22float2(*(__half2*)&xbA[cur][nt]);
            acc[nt][0] = biasv[nt].x + xa.x;
            acc[nt][1] = biasv[nt].y + xa.y;
            acc[nt][2] = 0.f;
            acc[nt][3] = 0.f;
        }

        // reissue buf[cur] for t+2
        {
            const size_t tn = (size_t)((t + 2 < Tsz) ? t + 2 : Tsz - 1) * tstep;
#pragma unroll
            for (int nt = 0; nt < 4; nt++)
                xbA[cur][nt] = *(const uint32_t*)(g_xp16 + tn + baseA0 + nt * 8);
        }

        // matvec (rows 8-15 of h are zero)
        const uint32_t aL = sHA + cur * HBUFB + a_lane_base;
        uint32_t ra[4][4];
        ldsm_x4(ra[0], aL + 0 * 32);
        ldsm_x4(ra[1], aL + 1 * 32);
        ldsm_x4(ra[2], aL + 2 * 32);
        ldsm_x4(ra[3], aL + 3 * 32);
#pragma unroll
        for (int kt = 0; kt < 4; kt++) {
            mma16816(acc[0], ra[kt], rbf[kt][0], rbf[kt][1]);
            mma16816(acc[1], ra[kt], rbf[kt][2], rbf[kt][3]);
            mma16816(acc[2], ra[kt], rbf[kt][4], rbf[kt][5]);
            mma16816(acc[3], ra[kt], rbf[kt][6], rbf[kt][7]);
        }

        // intra-warp exchange: even lanes get {g,o} of nt0/nt1 from odd;
        // odd lanes get {i,f} of nt2/nt3 from even. 4 shfls total.
        float x0 = __shfl_xor_sync(0xffffffffu, even ? acc[2][0] : acc[0][0], 1);
        float x1 = __shfl_xor_sync(0xffffffffu, even ? acc[2][1] : acc[0][1], 1);
        float x2 = __shfl_xor_sync(0xffffffffu, even ? acc[3][0] : acc[1][0], 1);
        float x3 = __shfl_xor_sync(0xffffffffu, even ? acc[3][1] : acc[1][1], 1);

        // cell A: even -> (row rq, unit uA) from nt0; odd -> from nt2
        float iA = even ? acc[0][0] : x0;
        float fA = even ? acc[0][1] : x1;
        float gA = even ? x0 : acc[2][0];
        float oA = even ? x1 : acc[2][1];
        // cell B: even -> nt1; odd -> nt3
        float iB = even ? acc[1][0] : x2;
        float fB = even ? acc[1][1] : x3;
        float gB = even ? x2 : acc[3][0];
        float oB = even ? x3 : acc[3][1];

        __half* hnext = (__half*)(sm + SM_HA + ((t + 1) & 1) * HBUFB);
        {
            float vi = sigm_ap(iA), vf = sigm_ap(fA);
            float vg = tanhap(gA),  vo = sigm_ap(oA);
            cA = fmaf(vf, cA, vi * vg);
            hnext[rq * HSTR + uA] = __float2half(vo * tanhap(cA));
        }
        {
            float vi = sigm_ap(iB), vf = sigm_ap(fB);
            float vg = tanhap(gB),  vo = sigm_ap(oB);
            cB = fmaf(vf, cB, vi * vg);
            hnext[rq * HSTR + uB] = __float2half(vo * tanhap(cB));
        }
        __syncthreads();
    }

    // fused head: warp w handles batch row r0 + w  (w = 0..7)
    {
        __half* hfin = (__half*)(sm + SM_HA + (Tsz & 1) * HBUFB);
        float y1 = b1[lane];
#pragma unroll
        for (int k = 0; k < Hsz; k++)
            y1 += W1[lane * Hsz + k] * __half2float(hfin[w * HSTR + k]);
        y1 = fmaxf(y1, 0.f);
        float z = y1 * W2[lane];
#pragma unroll
        for (int off = 16; off > 0; off >>= 1) z += __shfl_down_sync(0xffffffffu, z, off);
        if (lane == 0) out[r0 + w] = sigm_exact(z + b2[0]);
    }
}

// ===========================================================================
extern "C" void kernel_launch(void* const* d_in, const int* in_sizes, int n_in,
                              void* d_out, int out_size)
{
    const float* x   = (const float*)d_in[0];
    const float* Wih = (const float*)d_in[1];
    const float* Whh = (const float*)d_in[2];
    const float* bih = (const float*)d_in[3];
    const float* bhh = (const float*)d_in[4];
    const float* W1  = (const float*)d_in[5];
    const float* b1  = (const float*)d_in[6];
    const float* W2  = (const float*)d_in[7];
    const float* b2  = (const float*)d_in[8];
    float* out = (float*)d_out;

    static bool attr_set = false;
    if (!attr_set) {
        cudaFuncSetAttribute(xproj_tc, cudaFuncAttributeMaxDynamicSharedMemorySize, GEMM_SMEM);
        attr_set = true;
    }
    xproj_tc<<<GEMM_CTAS, 512, GEMM_SMEM>>>(x, Wih);
    lstm_rec_tc<<<Bsz / RB, 256>>>(Whh, bih, bhh, W1, b1, W2, b2, out);
}